// round 15
// baseline (speedup 1.0000x reference)
#include <cuda_runtime.h>
#include <math.h>

#define PI_D 3.14159265358979323846

// ---------------------------------------------------------------------------
// SO(3) convolution, B=24 (grid 48), F_IN=F_OUT=16, BATCH=16, P=12 rotations.
// NSPEC = sum_{l<24} (2l+1)^2 = 18424, Z = 256.
// Hermitian + conjugate-pair folding exploited in every DFT stage.
// Fz stored canonical-only (m >= l); expand mirrors the one needed row.
// ---------------------------------------------------------------------------

namespace so3 {
constexpr int    NB     = 48;
constexpr int    NSPEC  = 18424;
constexpr int    NZ     = 256;
constexpr int    NUV    = NB * NB;          // 2304
constexpr int    NSLICE = NZ * NB;          // 12288
constexpr size_t SZW    = 48ull * NSPEC;    // floats per wigner stack
constexpr size_t OFF_WW = 0;                // weighted wigner (forward)
constexpr size_t OFF_WU = SZW;              // (2l+1)-scaled wigner (inverse)
constexpr size_t OFF_RFT = 2 * SZW;         // rft matrix, float2 [12][NSPEC]
constexpr size_t OFF_WF  = OFF_RFT + 2ull * 12 * NSPEC;  // DFT twiddles float2[48*48]
constexpr size_t TABSZ   = OFF_WF + 2ull * NUV;
constexpr float  SCALING = 0.07216878364870323f;  // 1/sqrt(12*16)
}
using namespace so3;

__device__ __forceinline__ int    base_l(int l) { return (4 * l * l * l - l) / 3; }
__device__ __forceinline__ size_t base3(int l)  { return (size_t)l * l * (2 * l * l - 1); }

__device__ __forceinline__ void cmac(float2& c, const float2 a, const float2 b) {
    c.x = fmaf(a.x, b.x, fmaf(-a.y, b.y, c.x));
    c.y = fmaf(a.x, b.y, fmaf( a.y, b.x, c.y));
}

// ------------------------- static device scratch ---------------------------
__device__ float  g_tab[TABSZ];                          // ~8.9 MB
__device__ double g_coef[662976];                        // wigner coefs, fp64
__device__ float4 g_X4[(size_t)NZ * 48 * NUV / 2];       // 226 MB (X, then S)
__device__ float2 g_Fx[(size_t)NSPEC * NZ];
__device__ float2 g_Fy[(size_t)NSPEC * NZ];
__device__ float2 g_Fz[(size_t)NSPEC * NZ];

// =============================== init ======================================

__global__ void k_init_wf() {
    int t = blockIdx.x * 256 + threadIdx.x;
    if (t < NUV) {
        int a = t / 48, b = t - 48 * a;
        double ang = -2.0 * PI_D * (double)(a * b) / 48.0;
        g_tab[OFF_WF + 2 * t]     = (float)cos(ang);
        g_tab[OFF_WF + 2 * t + 1] = (float)sin(ang);
    }
}

// Only canonical quadrant (i <= jj, i + jj <= L-1) is ever read by k_init_wig.
__global__ void k_init_coef() {
    int l = blockIdx.x;
    int L = 2 * l + 1;
    __shared__ double LNF[101];
    int t = threadIdx.x;
    for (int i = t; i < 101; i += 256) LNF[i] = lgamma((double)i + 1.0);
    __syncthreads();
    double* coef = g_coef + base3(l);
    for (int e = t; e < L * L; e += 256) {
        int i = e / L, jj = e - i * L;
        if (i > jj || i + jj > L - 1) continue;   // canonical only
        int mp = i - l, mm = jj - l;
        int kmin = max(0, mm - mp), kmax = min(l + mm, l - mp);
        for (int k = kmin; k <= kmax; k++) {
            double ln = 0.5 * (LNF[l + mp] + LNF[l - mp] + LNF[l + mm] + LNF[l - mm])
                      - LNF[l + mm - k] - LNF[k] - LNF[mp - mm + k] - LNF[l - mp - k];
            double v = exp(ln);
            if ((mp - mm + k) & 1) v = -v;
            coef[(size_t)e * L + k] = v;
        }
    }
}

// jb < 48: SOFT beta grid (weighted + (2l+1)-scaled tables)
// jb = 48, 49: the two grid betas -> RFT matrix (with exact pi/3 alpha phases)
__global__ void k_init_wig() {
    int l  = blockIdx.y;
    int L  = 2 * l + 1;
    int jb = blockIdx.x;
    __shared__ double cp[47], sp[47];
    __shared__ double sw;
    int t = threadIdx.x;
    if (t == 0) {
        double beta = (jb < 48) ? ((double)jb + 0.5) * PI_D / 48.0
                                : ((jb == 48) ? PI_D / 16.0 : PI_D / 8.0);
        double c = cos(beta * 0.5), s = sin(beta * 0.5);
        double pc = 1.0, ps = 1.0;
        for (int e = 0; e < 47; e++) { cp[e] = pc; sp[e] = ps; pc *= c; ps *= s; }
        if (jb < 48) {
            double ssum = 0.0;
            for (int k = 0; k < 24; k++)
                ssum += sin((double)(2 * jb + 1) * (double)(2 * k + 1) * PI_D / 96.0)
                        / (double)(2 * k + 1);
            sw = (2.0 / 24.0) * sin(PI_D * (double)(2 * jb + 1) / 96.0) * ssum * 0.5;
        } else {
            sw = 0.0;
        }
    }
    __syncthreads();
    const double CT6[6] = {1.0, 0.5, -0.5, -1.0, -0.5, 0.5};
    const double ST6[6] = {0.0,  0.8660254037844386,  0.8660254037844386,
                           0.0, -0.8660254037844386, -0.8660254037844386};
    const double* coef = g_coef + base3(l);
    size_t wb = 48ull * (size_t)base_l(l);
    for (int e = t; e < L * L; e += 256) {
        int i = e / L, jj = e - i * L;
        if (i > jj || i + jj > L - 1) continue;   // canonical quadrant
        int mp = i - l, mm = jj - l;
        int kmin = max(0, mm - mp), kmax = min(l + mm, l - mp);
        double sum = 0.0;
        for (int k = kmin; k <= kmax; k++)
            sum += coef[(size_t)e * L + k] * cp[2 * l - 2 * k + mm - mp] * sp[2 * k + mp - mm];
        double sgn = ((i - jj) & 1) ? -sum : sum;
        int    rr[4]  = { i, jj, L - 1 - i, L - 1 - jj };
        int    ccn[4] = { jj, i, L - 1 - jj, L - 1 - i };
        double vl[4]  = { sum, sgn, sgn, sum };
        if (jb < 48) {
#pragma unroll
            for (int q = 0; q < 4; q++) {
                size_t idx = wb + ((size_t)jb * L + rr[q]) * L + ccn[q];
                g_tab[OFF_WW + idx] = (float)(vl[q] * sw);
                g_tab[OFF_WU + idx] = (float)(vl[q] * (double)L);
            }
        } else {
            int ib = jb - 48;
#pragma unroll
            for (int q = 0; q < 4; q++) {
                size_t s = (size_t)base_l(l) + (size_t)rr[q] * L + ccn[q];
                int mpr = rr[q] - l;
                for (int ia = 0; ia < 6; ia++) {
                    int n = ((mpr * ia) % 6 + 6) % 6;
                    int p = ia * 2 + ib;
                    g_tab[OFF_RFT + 2 * ((size_t)p * NSPEC + s)]     = (float)(CT6[n] * vl[q]);
                    g_tab[OFF_RFT + 2 * ((size_t)p * NSPEC + s) + 1] = (float)(ST6[n] * vl[q]);
                }
            }
        }
    }
}

// ========================== forward 2-D DFT ================================
// Two slices per block. Stage A: real even/odd fold over q, T cols v in [0,25],
// 6p x 2v tiles (208 items, one pass). Stage B: conjugate-pair fold over p;
// only X rows u in [0,23] stored.

__global__ void __launch_bounds__(256) k_fft_fwd(const float* __restrict__ x) {
    __shared__ __align__(16) float  sx[2][NUV];
    __shared__ __align__(16) float2 sW[NUV];
    __shared__ __align__(16) float2 sT[2][48 * 26];
    int t = threadIdx.x;
    size_t slice0 = (size_t)blockIdx.x * 2;
    const float2* Wf = (const float2*)(g_tab + OFF_WF);
    const float* x0 = x + slice0 * NUV;
    for (int i = t; i < NUV; i += 256) {
        sx[0][i] = x0[i];
        sx[1][i] = x0[NUV + i];
        sW[i] = Wf[i];
    }
    __syncthreads();
    // stage A: T[p,v] = x0 + (-1)^v x24 + sum_{q=1..23} (e_q c, o_q (-s))
    if (t < 208) {
        int s = (t >= 104);
        int ii = t - 104 * s;
        int p0 = 6 * (ii / 13), v0 = 2 * (ii % 13);   // v0 even, cols v0, v0+1
        const float* xs = sx[s];
        float2 acc[6][2];
#pragma unroll
        for (int a = 0; a < 6; a++) {
            float xa0  = xs[(p0 + a) * 48];
            float xa24 = xs[(p0 + a) * 48 + 24];
            acc[a][0] = make_float2(xa0 + xa24, 0.f);   // v even
            acc[a][1] = make_float2(xa0 - xa24, 0.f);   // v odd
        }
#pragma unroll
        for (int q = 1; q < 24; q++) {
            float2 w0 = sW[q * 48 + v0];
            float2 w1 = sW[q * 48 + v0 + 1];
#pragma unroll
            for (int a = 0; a < 6; a++) {
                float xa = xs[(p0 + a) * 48 + q];
                float xb = xs[(p0 + a) * 48 + 48 - q];
                float e = xa + xb;
                float o = xa - xb;
                acc[a][0].x = fmaf(e, w0.x, acc[a][0].x);
                acc[a][0].y = fmaf(o, w0.y, acc[a][0].y);
                acc[a][1].x = fmaf(e, w1.x, acc[a][1].x);
                acc[a][1].y = fmaf(o, w1.y, acc[a][1].y);
            }
        }
#pragma unroll
        for (int a = 0; a < 6; a++)
#pragma unroll
            for (int b = 0; b < 2; b++) sT[s][(p0 + a) * 26 + v0 + b] = acc[a][b];
    }
    __syncthreads();
    // stage B: X[u,v] = sum_p T[p,v] W[p,u]; fold p with 48-p. 3x3 tiles,
    // all 256 threads: s = t>>7, u0 = 3*(t128>>4) in [0,21], v0 = 3*(t128&15).
    {
        int s = t >> 7, t128 = t & 127;
        int u0 = 3 * (t128 >> 4);
        int v0 = 3 * (t128 & 15);
        int   cols[3];
        float sg[3];
#pragma unroll
        for (int b = 0; b < 3; b++) {
            int v = v0 + b;
            cols[b] = (v <= 25) ? v : 48 - v;
            sg[b]   = (v <= 25) ? 1.f : -1.f;
        }
        float2 c[3][3];
#pragma unroll
        for (int b = 0; b < 3; b++) {
            float2 t0  = sT[s][cols[b]];            // p = 0
            float2 t24 = sT[s][24 * 26 + cols[b]];  // p = 24
            t0.y *= sg[b]; t24.y *= sg[b];
#pragma unroll
            for (int a = 0; a < 3; a++) {
                float su = ((u0 + a) & 1) ? -1.f : 1.f;
                c[a][b] = make_float2(t0.x + su * t24.x, t0.y + su * t24.y);
            }
        }
#pragma unroll 2
        for (int p = 1; p < 24; p++) {
            float Ex[3], Ey[3], Ox[3], Oy[3];
#pragma unroll
            for (int b = 0; b < 3; b++) {
                float2 t1 = sT[s][p * 26 + cols[b]];
                float2 t2 = sT[s][(48 - p) * 26 + cols[b]];
                t1.y *= sg[b]; t2.y *= sg[b];
                Ex[b] = t1.x + t2.x; Ey[b] = t1.y + t2.y;
                Ox[b] = t1.x - t2.x; Oy[b] = t1.y - t2.y;
            }
#pragma unroll
            for (int a = 0; a < 3; a++) {
                float2 w = sW[p * 48 + u0 + a];
#pragma unroll
                for (int b = 0; b < 3; b++) {
                    c[a][b].x = fmaf(Ex[b], w.x, fmaf(-Oy[b], w.y, c[a][b].x));
                    c[a][b].y = fmaf(Ey[b], w.x, fmaf( Ox[b], w.y, c[a][b].y));
                }
            }
        }
        float2* Xo = (float2*)g_X4 + (slice0 + s) * NUV;
#pragma unroll
        for (int a = 0; a < 3; a++)
#pragma unroll
            for (int b = 0; b < 3; b++)
                Xo[(size_t)(u0 + a) * 48 + v0 + b] = c[a][b];
    }
}

// ========================== beta contraction ===============================
// Canonical u = su in [0,23]; mirror writes Fx[l,-su,-sv] = (-1)^{su-sv} conj.

__global__ void __launch_bounds__(256) k_contract() {
    int half = blockIdx.x;            // l in [12*half, 12*half+12)
    int u  = blockIdx.y;              // = su in 0..23
    int v0 = 2 * blockIdx.z;
    int su = u;
    int l0 = 12 * half;
    int svs[2], lmin[2];
#pragma unroll
    for (int vv = 0; vv < 2; vv++) {
        int v = v0 + vv;
        svs[vv] = (v < 24) ? v : v - 48;
        lmin[vv] = (svs[vv] == -24) ? 24 : max(su, abs(svs[vv]));
    }
    __shared__ __align__(16) float ws[48][24];   // [j][2*(l-l0)+vv]
    int t = threadIdx.x;
    for (int i = t; i < 48 * 24; i += 256) {
        int j = i / 24, r = i - 24 * j;
        int dl = r >> 1, vv = r & 1;
        int l = l0 + dl;
        float w = 0.f;
        if (l >= lmin[vv]) {
            int L = 2 * l + 1;
            w = g_tab[OFF_WW + 48ull * (size_t)base_l(l) + ((size_t)j * L + (su + l)) * L + (svs[vv] + l)];
        }
        ws[j][r] = w;
    }
    __syncthreads();
    float4 acc[12];
#pragma unroll
    for (int d = 0; d < 12; d++) acc[d] = make_float4(0.f, 0.f, 0.f, 0.f);
    const float4* Xp = g_X4 + ((size_t)t * 48 * NUV + (size_t)u * 48 + v0) / 2;
#pragma unroll 8
    for (int j = 0; j < 48; j++) {
        float4 xv = Xp[(size_t)j * (NUV / 2)];
        const float2* wj = (const float2*)ws[j];
#pragma unroll
        for (int d = 0; d < 12; d++) {
            float2 w = wj[d];
            acc[d].x = fmaf(w.x, xv.x, acc[d].x);
            acc[d].y = fmaf(w.x, xv.y, acc[d].y);
            acc[d].z = fmaf(w.y, xv.z, acc[d].z);
            acc[d].w = fmaf(w.y, xv.w, acc[d].w);
        }
    }
#pragma unroll
    for (int d = 0; d < 12; d++) {
        int l = l0 + d;
        int L = 2 * l + 1;
        size_t bs = (size_t)base_l(l);
#pragma unroll
        for (int vv = 0; vv < 2; vv++) {
            if (l < lmin[vv]) continue;
            float2 a = vv ? make_float2(acc[d].z, acc[d].w)
                          : make_float2(acc[d].x, acc[d].y);
            g_Fx[(bs + (size_t)(su + l) * L + (svs[vv] + l)) * NZ + t] = a;
            if (su > 0) {
                float sgn = ((su - svs[vv]) & 1) ? -1.f : 1.f;
                g_Fx[(bs + (size_t)(l - su) * L + (l - svs[vv])) * NZ + t] =
                    make_float2(sgn * a.x, -sgn * a.y);
            }
        }
    }
}

// ================================ Fy ========================================

__global__ void __launch_bounds__(256) k_fy(const float* __restrict__ kern) {
    __shared__ float2 srft[12];
    int t = threadIdx.x;
    int f = t >> 4, g = t & 15;
    float kv[12];
#pragma unroll
    for (int p = 0; p < 12; p++) kv[p] = kern[(f * 16 + g) * 12 + p] * SCALING;
    const float2* rft = (const float2*)(g_tab + OFF_RFT);
    for (int s = blockIdx.x; s < NSPEC; s += gridDim.x) {
        if (t < 12) srft[t] = rft[(size_t)t * NSPEC + s];
        __syncthreads();
        float2 a = make_float2(0.f, 0.f);
#pragma unroll
        for (int p = 0; p < 12; p++) {
            a.x = fmaf(kv[p], srft[p].x, a.x);
            a.y = fmaf(kv[p], srft[p].y, a.y);
        }
        g_Fy[(size_t)s * NZ + t] = a;
        __syncthreads();
    }
}

// =============================== so3_mm ====================================
// Computes only tiles with canonical rows (m0+7 >= l); expand mirrors the
// single non-canonical row it needs.

__global__ void __launch_bounds__(256) k_mm_all() {
    int l = blockIdx.z;
    int L = 2 * l + 1;
    int n0 = 4 * blockIdx.x;
    int m0 = 8 * blockIdx.y;
    if (m0 >= L || n0 >= L) return;
    if (m0 + 7 < l) return;           // never read -> skip
    size_t base = (size_t)base_l(l);
    __shared__ float2 Xs[8][256], Ys[4][256];
    int t = threadIdx.x;
    int b = t >> 4, g = t & 15;
    float2 c[8][4];
#pragma unroll
    for (int a = 0; a < 8; a++)
#pragma unroll
        for (int bb = 0; bb < 4; bb++) c[a][bb] = make_float2(0.f, 0.f);
    const float2 z2 = make_float2(0.f, 0.f);
    for (int k = 0; k < L; k++) {
#pragma unroll
        for (int a = 0; a < 8; a++)
            Xs[a][t] = (m0 + a < L) ? g_Fx[(base + (size_t)(m0 + a) * L + k) * NZ + t] : z2;
#pragma unroll
        for (int a = 0; a < 4; a++)
            Ys[a][t] = (n0 + a < L) ? g_Fy[(base + (size_t)k * L + (n0 + a)) * NZ + t] : z2;
        __syncthreads();
#pragma unroll
        for (int f = 0; f < 16; f++) {
            float2 xr[8], yr[4];
#pragma unroll
            for (int a = 0; a < 4; a++) yr[a] = Ys[a][f * 16 + g];
#pragma unroll
            for (int a = 0; a < 8; a++) xr[a] = Xs[a][b * 16 + f];
#pragma unroll
            for (int a = 0; a < 8; a++)
#pragma unroll
                for (int bb = 0; bb < 4; bb++) cmac(c[a][bb], xr[a], yr[bb]);
        }
        __syncthreads();
    }
#pragma unroll
    for (int a = 0; a < 8; a++) {
        if (m0 + a >= L) continue;
#pragma unroll
        for (int bb = 0; bb < 4; bb++) {
            if (n0 + bb >= L) continue;
            g_Fz[(base + (size_t)(m0 + a) * L + (n0 + bb)) * NZ + t] = c[a][bb];
        }
    }
}

// =============================== expand ====================================
// Only S rows u in [0,24] are needed by the Hermitian inverse DFT.
// su >= 0 always; the one non-canonical Fz access (su==0, sv<0) is mirrored:
// Fz[l, l+sv] = (-1)^{sv} conj Fz[l, l-sv].

__global__ void __launch_bounds__(256) k_expand() {
    int u  = blockIdx.x;              // 0..24
    int v0 = 2 * blockIdx.y;
    int su = (u < 24) ? u : u - 48;
    bool uok = (su != -24);
    int t = threadIdx.x;
    int lmin[2];
#pragma unroll
    for (int vv = 0; vv < 2; vv++) {
        int v = v0 + vv;
        int sv = (v < 24) ? v : v - 48;
        lmin[vv] = (uok && sv != -24) ? max(abs(su), abs(sv)) : 24;
    }
    __shared__ __align__(16) float ws[48][48];   // [j][2*l+vv]
    for (int i = t; i < 48 * 48; i += 256) {
        int j = i / 48, r = i - 48 * j;
        int l = r >> 1, vv = r & 1;
        float w = 0.f;
        if (l >= lmin[vv]) {
            int L = 2 * l + 1;
            int v = v0 + vv;
            int sv = (v < 24) ? v : v - 48;
            w = g_tab[OFF_WU + 48ull * (size_t)base_l(l) + ((size_t)j * L + (su + l)) * L + (sv + l)];
        }
        ws[j][r] = w;
    }
    __syncthreads();
    float4 fv[24];
#pragma unroll
    for (int l = 0; l < 24; l++) {
        fv[l] = make_float4(0.f, 0.f, 0.f, 0.f);
        int L = 2 * l + 1;
        size_t bs = (size_t)base_l(l);
#pragma unroll
        for (int vv = 0; vv < 2; vv++) {
            if (l < lmin[vv]) continue;
            int v = v0 + vv;
            int sv = (v < 24) ? v : v - 48;
            float2 f2;
            if (su == 0 && sv < 0) {
                f2 = g_Fz[(bs + (size_t)l * L + (l - sv)) * NZ + t];
                float sgn = (sv & 1) ? -1.f : 1.f;
                f2 = make_float2(sgn * f2.x, -sgn * f2.y);
            } else {
                f2 = g_Fz[(bs + (size_t)(su + l) * L + (sv + l)) * NZ + t];
            }
            if (vv) { fv[l].z = f2.x; fv[l].w = f2.y; }
            else    { fv[l].x = f2.x; fv[l].y = f2.y; }
        }
    }
    float4* Sp = g_X4 + ((size_t)t * 48 * NUV + (size_t)u * 48 + v0) / 2;
#pragma unroll 4
    for (int j = 0; j < 48; j++) {
        const float2* wj = (const float2*)ws[j];
        float4 a = make_float4(0.f, 0.f, 0.f, 0.f);
#pragma unroll
        for (int l = 0; l < 24; l++) {
            float2 w = wj[l];
            a.x = fmaf(w.x, fv[l].x, a.x);
            a.y = fmaf(w.x, fv[l].y, a.y);
            a.z = fmaf(w.y, fv[l].z, a.z);
            a.w = fmaf(w.y, fv[l].w, a.w);
        }
        Sp[(size_t)j * (NUV / 2)] = a;
    }
}

// ========================== inverse 2-D DFT ================================
// Two slices per block. Stage A: fold v with 48-v. Stage B: fold p with 48-p:
// out[p] = P + Q, out[48-p] = P - Q. Stage B: 2p x 6q tiles (208, one pass).

__global__ void __launch_bounds__(256) k_fft_inv(float* __restrict__ out) {
    __shared__ __align__(16) float2 sS[2][26 * 48];
    __shared__ __align__(16) float2 sW[NUV];
    int t = threadIdx.x;
    size_t slice0 = (size_t)blockIdx.x * 2;
    const float2* Wf = (const float2*)(g_tab + OFF_WF);
    const float2* S0 = (const float2*)g_X4 + slice0 * NUV;
    const float2 z2 = make_float2(0.f, 0.f);
    for (int i = t; i < 26 * 48; i += 256) {
        bool valid = i < 25 * 48;
        sS[0][i] = valid ? S0[i] : z2;
        sS[1][i] = valid ? S0[NUV + i] : z2;
    }
    for (int i = t; i < NUV; i += 256) sW[i] = Wf[i];
    __syncthreads();
    // stage A: T[u,q] = sum_v S[u,v] conj(W[v,q]); fold v & 48-v.
    int tu = t >> 4;
    int q0 = 3 * (t & 15);
    int u0 = 2 * tu;
    float2 c[2][2][3];
    if (tu < 13) {
#pragma unroll
        for (int s = 0; s < 2; s++)
#pragma unroll
            for (int a = 0; a < 2; a++) {
                float2 S0v  = sS[s][(u0 + a) * 48];
                float2 S24v = sS[s][(u0 + a) * 48 + 24];
#pragma unroll
                for (int b = 0; b < 3; b++) {
                    float sq = ((q0 + b) & 1) ? -1.f : 1.f;
                    c[s][a][b] = make_float2(S0v.x + sq * S24v.x, S0v.y + sq * S24v.y);
                }
            }
#pragma unroll 2
        for (int v = 1; v < 24; v++) {
            float2 wq[3];
#pragma unroll
            for (int b = 0; b < 3; b++) wq[b] = sW[v * 48 + q0 + b];
#pragma unroll
            for (int s = 0; s < 2; s++)
#pragma unroll
                for (int a = 0; a < 2; a++) {
                    float2 S1 = sS[s][(u0 + a) * 48 + v];
                    float2 S2 = sS[s][(u0 + a) * 48 + 48 - v];
                    float Ex = S1.x + S2.x, Ey = S1.y + S2.y;
                    float Ox = S1.x - S2.x, Oy = S1.y - S2.y;
#pragma unroll
                    for (int b = 0; b < 3; b++) {
                        c[s][a][b].x = fmaf(Ex, wq[b].x, fmaf( Oy, wq[b].y, c[s][a][b].x));
                        c[s][a][b].y = fmaf(Ey, wq[b].x, fmaf(-Ox, wq[b].y, c[s][a][b].y));
                    }
                }
        }
    }
    __syncthreads();  // all sS reads done; reuse sS for scaled T
    if (tu < 13) {
#pragma unroll
        for (int a = 0; a < 2; a++) {
            int uu = u0 + a;
            float f = (uu == 0 || uu == 24) ? 1.f : 2.f;
#pragma unroll
            for (int s = 0; s < 2; s++)
#pragma unroll
                for (int b = 0; b < 3; b++)
                    sS[s][uu * 48 + q0 + b] = make_float2(f * c[s][a][b].x, f * c[s][a][b].y);
        }
    }
    __syncthreads();
    // stage B: P = sum_u T'x w.x, Q = sum_u T'y w.y;
    //          out[p] = (P+Q)/2304, out[48-p] = (P-Q)/2304.  2p x 6q tiles.
    if (t < 208) {
        int s = (t >= 104);
        int ii = t - 104 * s;
        int p0 = 2 * (ii / 8);       // 0,2,...,24
        int qq0 = 6 * (ii % 8);      // 0,6,...,42
        float P[2][6], Q[2][6];
#pragma unroll
        for (int a = 0; a < 2; a++)
#pragma unroll
            for (int b = 0; b < 6; b++) { P[a][b] = 0.f; Q[a][b] = 0.f; }
#pragma unroll 5
        for (int u = 0; u < 25; u++) {
            float2 wv[2];
#pragma unroll
            for (int a = 0; a < 2; a++) wv[a] = sW[u * 48 + p0 + a];
#pragma unroll
            for (int b = 0; b < 6; b++) {
                float2 tw = sS[s][u * 48 + qq0 + b];
#pragma unroll
                for (int a = 0; a < 2; a++) {
                    P[a][b] = fmaf(tw.x, wv[a].x, P[a][b]);
                    Q[a][b] = fmaf(tw.y, wv[a].y, Q[a][b]);
                }
            }
        }
        const float scale = 1.f / 2304.f;
        float* op = out + (slice0 + s) * NUV;
#pragma unroll
        for (int a = 0; a < 2; a++) {
            int p = p0 + a;
            if (p > 24) continue;
#pragma unroll
            for (int b = 0; b < 6; b++) {
                op[p * 48 + qq0 + b] = (P[a][b] + Q[a][b]) * scale;
                if (p >= 1 && p <= 23)
                    op[(48 - p) * 48 + qq0 + b] = (P[a][b] - Q[a][b]) * scale;
            }
        }
    }
}

// ============================== launch ======================================

extern "C" void kernel_launch(void* const* d_in, const int* in_sizes, int n_in,
                              void* d_out, int out_size) {
    const float* x    = (const float*)d_in[0];
    const float* kern = (const float*)d_in[1];
    if (n_in >= 2 && in_sizes[0] == 16 * 16 * 12) {
        x = (const float*)d_in[1];
        kern = (const float*)d_in[0];
    }
    float* out = (float*)d_out;

    k_init_wf  <<<9, 256>>>();
    k_init_coef<<<24, 256>>>();
    k_init_wig <<<dim3(50, 24), 256>>>();

    k_fft_fwd  <<<NSLICE / 2, 256>>>(x);
    k_contract <<<dim3(2, 24, 24), 256>>>();
    k_fy       <<<512, 256>>>(kern);
    k_mm_all   <<<dim3(12, 6, 24), 256>>>();
    k_expand   <<<dim3(25, 24), 256>>>();
    k_fft_inv  <<<NSLICE / 2, 256>>>(out);
}

// round 16
// speedup vs baseline: 1.0664x; 1.0664x over previous
#include <cuda_runtime.h>
#include <math.h>

#define PI_D 3.14159265358979323846

// ---------------------------------------------------------------------------
// SO(3) convolution, B=24 (grid 48), F_IN=F_OUT=16, BATCH=16, P=12 rotations.
// NSPEC = sum_{l<24} (2l+1)^2 = 18424, Z = 256.
// Hermitian + conjugate-pair folding exploited in every DFT stage.
// Fz stored canonical-only (m >= l); expand mirrors the one needed row.
// ---------------------------------------------------------------------------

namespace so3 {
constexpr int    NB     = 48;
constexpr int    NSPEC  = 18424;
constexpr int    NZ     = 256;
constexpr int    NUV    = NB * NB;          // 2304
constexpr int    NSLICE = NZ * NB;          // 12288
constexpr size_t SZW    = 48ull * NSPEC;    // floats per wigner stack
constexpr size_t OFF_WW = 0;                // weighted wigner (forward)
constexpr size_t OFF_WU = SZW;              // (2l+1)-scaled wigner (inverse)
constexpr size_t OFF_RFT = 2 * SZW;         // rft matrix, float2 [12][NSPEC]
constexpr size_t OFF_WF  = OFF_RFT + 2ull * 12 * NSPEC;  // DFT twiddles float2[48*48]
constexpr size_t TABSZ   = OFF_WF + 2ull * NUV;
constexpr float  SCALING = 0.07216878364870323f;  // 1/sqrt(12*16)
}
using namespace so3;

__device__ __forceinline__ int    base_l(int l) { return (4 * l * l * l - l) / 3; }
__device__ __forceinline__ size_t base3(int l)  { return (size_t)l * l * (2 * l * l - 1); }

__device__ __forceinline__ void cmac(float2& c, const float2 a, const float2 b) {
    c.x = fmaf(a.x, b.x, fmaf(-a.y, b.y, c.x));
    c.y = fmaf(a.x, b.y, fmaf( a.y, b.x, c.y));
}

// ------------------------- static device scratch ---------------------------
__device__ float  g_tab[TABSZ];                          // ~8.9 MB
__device__ double g_coef[662976];                        // wigner coefs, fp64
__device__ float4 g_X4[(size_t)NZ * 48 * NUV / 2];       // 226 MB (X, then S)
__device__ float2 g_Fx[(size_t)NSPEC * NZ];
__device__ float2 g_Fy[(size_t)NSPEC * NZ];
__device__ float2 g_Fz[(size_t)NSPEC * NZ];

// =============================== init ======================================

__global__ void k_init_wf() {
    int t = blockIdx.x * 256 + threadIdx.x;
    if (t < NUV) {
        int a = t / 48, b = t - 48 * a;
        double ang = -2.0 * PI_D * (double)(a * b) / 48.0;
        g_tab[OFF_WF + 2 * t]     = (float)cos(ang);
        g_tab[OFF_WF + 2 * t + 1] = (float)sin(ang);
    }
}

// Only canonical quadrant (i <= jj, i + jj <= L-1) is ever read by k_init_wig.
__global__ void k_init_coef() {
    int l = blockIdx.x;
    int L = 2 * l + 1;
    __shared__ double LNF[101];
    int t = threadIdx.x;
    for (int i = t; i < 101; i += 256) LNF[i] = lgamma((double)i + 1.0);
    __syncthreads();
    double* coef = g_coef + base3(l);
    for (int e = t; e < L * L; e += 256) {
        int i = e / L, jj = e - i * L;
        if (i > jj || i + jj > L - 1) continue;   // canonical only
        int mp = i - l, mm = jj - l;
        int kmin = max(0, mm - mp), kmax = min(l + mm, l - mp);
        for (int k = kmin; k <= kmax; k++) {
            double ln = 0.5 * (LNF[l + mp] + LNF[l - mp] + LNF[l + mm] + LNF[l - mm])
                      - LNF[l + mm - k] - LNF[k] - LNF[mp - mm + k] - LNF[l - mp - k];
            double v = exp(ln);
            if ((mp - mm + k) & 1) v = -v;
            coef[(size_t)e * L + k] = v;
        }
    }
}

// jb < 48: SOFT beta grid (weighted + (2l+1)-scaled tables)
// jb = 48, 49: the two grid betas -> RFT matrix (with exact pi/3 alpha phases)
__global__ void k_init_wig() {
    int l  = blockIdx.y;
    int L  = 2 * l + 1;
    int jb = blockIdx.x;
    __shared__ double cp[47], sp[47];
    __shared__ double sw;
    int t = threadIdx.x;
    if (t == 0) {
        double beta = (jb < 48) ? ((double)jb + 0.5) * PI_D / 48.0
                                : ((jb == 48) ? PI_D / 16.0 : PI_D / 8.0);
        double c = cos(beta * 0.5), s = sin(beta * 0.5);
        double pc = 1.0, ps = 1.0;
        for (int e = 0; e < 47; e++) { cp[e] = pc; sp[e] = ps; pc *= c; ps *= s; }
        if (jb < 48) {
            double ssum = 0.0;
            for (int k = 0; k < 24; k++)
                ssum += sin((double)(2 * jb + 1) * (double)(2 * k + 1) * PI_D / 96.0)
                        / (double)(2 * k + 1);
            sw = (2.0 / 24.0) * sin(PI_D * (double)(2 * jb + 1) / 96.0) * ssum * 0.5;
        } else {
            sw = 0.0;
        }
    }
    __syncthreads();
    const double CT6[6] = {1.0, 0.5, -0.5, -1.0, -0.5, 0.5};
    const double ST6[6] = {0.0,  0.8660254037844386,  0.8660254037844386,
                           0.0, -0.8660254037844386, -0.8660254037844386};
    const double* coef = g_coef + base3(l);
    size_t wb = 48ull * (size_t)base_l(l);
    for (int e = t; e < L * L; e += 256) {
        int i = e / L, jj = e - i * L;
        if (i > jj || i + jj > L - 1) continue;   // canonical quadrant
        int mp = i - l, mm = jj - l;
        int kmin = max(0, mm - mp), kmax = min(l + mm, l - mp);
        double sum = 0.0;
        for (int k = kmin; k <= kmax; k++)
            sum += coef[(size_t)e * L + k] * cp[2 * l - 2 * k + mm - mp] * sp[2 * k + mp - mm];
        double sgn = ((i - jj) & 1) ? -sum : sum;
        int    rr[4]  = { i, jj, L - 1 - i, L - 1 - jj };
        int    ccn[4] = { jj, i, L - 1 - jj, L - 1 - i };
        double vl[4]  = { sum, sgn, sgn, sum };
        if (jb < 48) {
#pragma unroll
            for (int q = 0; q < 4; q++) {
                size_t idx = wb + ((size_t)jb * L + rr[q]) * L + ccn[q];
                g_tab[OFF_WW + idx] = (float)(vl[q] * sw);
                g_tab[OFF_WU + idx] = (float)(vl[q] * (double)L);
            }
        } else {
            int ib = jb - 48;
#pragma unroll
            for (int q = 0; q < 4; q++) {
                size_t s = (size_t)base_l(l) + (size_t)rr[q] * L + ccn[q];
                int mpr = rr[q] - l;
                for (int ia = 0; ia < 6; ia++) {
                    int n = ((mpr * ia) % 6 + 6) % 6;
                    int p = ia * 2 + ib;
                    g_tab[OFF_RFT + 2 * ((size_t)p * NSPEC + s)]     = (float)(CT6[n] * vl[q]);
                    g_tab[OFF_RFT + 2 * ((size_t)p * NSPEC + s) + 1] = (float)(ST6[n] * vl[q]);
                }
            }
        }
    }
}

// ========================== forward 2-D DFT ================================
// Two slices per block. Stage A: real even/odd fold over q, T cols v in [0,25].
// Stage B: conjugate-pair fold over p; only X rows u in [0,23] stored.
// (Exact R14 tiling: 4p x 2v stage A, 3x3 stage B — regs 64, occ 48%.)

__global__ void __launch_bounds__(256) k_fft_fwd(const float* __restrict__ x) {
    __shared__ __align__(16) float  sx[2][NUV];
    __shared__ __align__(16) float2 sW[NUV];
    __shared__ __align__(16) float2 sT[2][48 * 26];
    int t = threadIdx.x;
    size_t slice0 = (size_t)blockIdx.x * 2;
    const float2* Wf = (const float2*)(g_tab + OFF_WF);
    const float* x0 = x + slice0 * NUV;
    for (int i = t; i < NUV; i += 256) {
        sx[0][i] = x0[i];
        sx[1][i] = x0[NUV + i];
        sW[i] = Wf[i];
    }
    __syncthreads();
    // stage A: T[p,v] = x0 + (-1)^v x24 + sum_{q=1..23} (e_q c, o_q (-s))
    for (int i = t; i < 312; i += 256) {
        int s = (i >= 156);
        int ii = i - 156 * s;
        int p0 = 4 * (ii / 13), v0 = 2 * (ii % 13);   // v0 even, cols v0, v0+1
        const float* xs = sx[s];
        float2 acc[4][2];
#pragma unroll
        for (int a = 0; a < 4; a++) {
            float xa0  = xs[(p0 + a) * 48];
            float xa24 = xs[(p0 + a) * 48 + 24];
            acc[a][0] = make_float2(xa0 + xa24, 0.f);   // v even
            acc[a][1] = make_float2(xa0 - xa24, 0.f);   // v odd
        }
#pragma unroll 4
        for (int q = 1; q < 24; q++) {
            float e[4], o[4];
#pragma unroll
            for (int a = 0; a < 4; a++) {
                float xa = xs[(p0 + a) * 48 + q];
                float xb = xs[(p0 + a) * 48 + 48 - q];
                e[a] = xa + xb;
                o[a] = xa - xb;
            }
            float2 w0 = sW[q * 48 + v0];
            float2 w1 = sW[q * 48 + v0 + 1];
#pragma unroll
            for (int a = 0; a < 4; a++) {
                acc[a][0].x = fmaf(e[a], w0.x, acc[a][0].x);
                acc[a][0].y = fmaf(o[a], w0.y, acc[a][0].y);
                acc[a][1].x = fmaf(e[a], w1.x, acc[a][1].x);
                acc[a][1].y = fmaf(o[a], w1.y, acc[a][1].y);
            }
        }
#pragma unroll
        for (int a = 0; a < 4; a++)
#pragma unroll
            for (int b = 0; b < 2; b++) sT[s][(p0 + a) * 26 + v0 + b] = acc[a][b];
    }
    __syncthreads();
    // stage B: X[u,v] = sum_p T[p,v] W[p,u]; fold p with 48-p. 3x3 tiles,
    // all 256 threads: s = t>>7, u0 = 3*(t128>>4) in [0,21], v0 = 3*(t128&15).
    {
        int s = t >> 7, t128 = t & 127;
        int u0 = 3 * (t128 >> 4);
        int v0 = 3 * (t128 & 15);
        int   cols[3];
        float sg[3];
#pragma unroll
        for (int b = 0; b < 3; b++) {
            int v = v0 + b;
            cols[b] = (v <= 25) ? v : 48 - v;
            sg[b]   = (v <= 25) ? 1.f : -1.f;
        }
        float2 c[3][3];
#pragma unroll
        for (int b = 0; b < 3; b++) {
            float2 t0  = sT[s][cols[b]];            // p = 0
            float2 t24 = sT[s][24 * 26 + cols[b]];  // p = 24
            t0.y *= sg[b]; t24.y *= sg[b];
#pragma unroll
            for (int a = 0; a < 3; a++) {
                float su = ((u0 + a) & 1) ? -1.f : 1.f;
                c[a][b] = make_float2(t0.x + su * t24.x, t0.y + su * t24.y);
            }
        }
#pragma unroll 2
        for (int p = 1; p < 24; p++) {
            float Ex[3], Ey[3], Ox[3], Oy[3];
#pragma unroll
            for (int b = 0; b < 3; b++) {
                float2 t1 = sT[s][p * 26 + cols[b]];
                float2 t2 = sT[s][(48 - p) * 26 + cols[b]];
                t1.y *= sg[b]; t2.y *= sg[b];
                Ex[b] = t1.x + t2.x; Ey[b] = t1.y + t2.y;
                Ox[b] = t1.x - t2.x; Oy[b] = t1.y - t2.y;
            }
#pragma unroll
            for (int a = 0; a < 3; a++) {
                float2 w = sW[p * 48 + u0 + a];
#pragma unroll
                for (int b = 0; b < 3; b++) {
                    c[a][b].x = fmaf(Ex[b], w.x, fmaf(-Oy[b], w.y, c[a][b].x));
                    c[a][b].y = fmaf(Ey[b], w.x, fmaf( Ox[b], w.y, c[a][b].y));
                }
            }
        }
        float2* Xo = (float2*)g_X4 + (slice0 + s) * NUV;
#pragma unroll
        for (int a = 0; a < 3; a++)
#pragma unroll
            for (int b = 0; b < 3; b++)
                Xo[(size_t)(u0 + a) * 48 + v0 + b] = c[a][b];
    }
}

// ========================== beta contraction ===============================
// Canonical u = su in [0,23]; mirror writes Fx[l,-su,-sv] = (-1)^{su-sv} conj.

__global__ void __launch_bounds__(256) k_contract() {
    int half = blockIdx.x;            // l in [12*half, 12*half+12)
    int u  = blockIdx.y;              // = su in 0..23
    int v0 = 2 * blockIdx.z;
    int su = u;
    int l0 = 12 * half;
    int svs[2], lmin[2];
#pragma unroll
    for (int vv = 0; vv < 2; vv++) {
        int v = v0 + vv;
        svs[vv] = (v < 24) ? v : v - 48;
        lmin[vv] = (svs[vv] == -24) ? 24 : max(su, abs(svs[vv]));
    }
    __shared__ __align__(16) float ws[48][24];   // [j][2*(l-l0)+vv]
    int t = threadIdx.x;
    for (int i = t; i < 48 * 24; i += 256) {
        int j = i / 24, r = i - 24 * j;
        int dl = r >> 1, vv = r & 1;
        int l = l0 + dl;
        float w = 0.f;
        if (l >= lmin[vv]) {
            int L = 2 * l + 1;
            w = g_tab[OFF_WW + 48ull * (size_t)base_l(l) + ((size_t)j * L + (su + l)) * L + (svs[vv] + l)];
        }
        ws[j][r] = w;
    }
    __syncthreads();
    float4 acc[12];
#pragma unroll
    for (int d = 0; d < 12; d++) acc[d] = make_float4(0.f, 0.f, 0.f, 0.f);
    const float4* Xp = g_X4 + ((size_t)t * 48 * NUV + (size_t)u * 48 + v0) / 2;
#pragma unroll 8
    for (int j = 0; j < 48; j++) {
        float4 xv = Xp[(size_t)j * (NUV / 2)];
        const float2* wj = (const float2*)ws[j];
#pragma unroll
        for (int d = 0; d < 12; d++) {
            float2 w = wj[d];
            acc[d].x = fmaf(w.x, xv.x, acc[d].x);
            acc[d].y = fmaf(w.x, xv.y, acc[d].y);
            acc[d].z = fmaf(w.y, xv.z, acc[d].z);
            acc[d].w = fmaf(w.y, xv.w, acc[d].w);
        }
    }
#pragma unroll
    for (int d = 0; d < 12; d++) {
        int l = l0 + d;
        int L = 2 * l + 1;
        size_t bs = (size_t)base_l(l);
#pragma unroll
        for (int vv = 0; vv < 2; vv++) {
            if (l < lmin[vv]) continue;
            float2 a = vv ? make_float2(acc[d].z, acc[d].w)
                          : make_float2(acc[d].x, acc[d].y);
            g_Fx[(bs + (size_t)(su + l) * L + (svs[vv] + l)) * NZ + t] = a;
            if (su > 0) {
                float sgn = ((su - svs[vv]) & 1) ? -1.f : 1.f;
                g_Fx[(bs + (size_t)(l - su) * L + (l - svs[vv])) * NZ + t] =
                    make_float2(sgn * a.x, -sgn * a.y);
            }
        }
    }
}

// ================================ Fy ========================================

__global__ void __launch_bounds__(256) k_fy(const float* __restrict__ kern) {
    __shared__ float2 srft[12];
    int t = threadIdx.x;
    int f = t >> 4, g = t & 15;
    float kv[12];
#pragma unroll
    for (int p = 0; p < 12; p++) kv[p] = kern[(f * 16 + g) * 12 + p] * SCALING;
    const float2* rft = (const float2*)(g_tab + OFF_RFT);
    for (int s = blockIdx.x; s < NSPEC; s += gridDim.x) {
        if (t < 12) srft[t] = rft[(size_t)t * NSPEC + s];
        __syncthreads();
        float2 a = make_float2(0.f, 0.f);
#pragma unroll
        for (int p = 0; p < 12; p++) {
            a.x = fmaf(kv[p], srft[p].x, a.x);
            a.y = fmaf(kv[p], srft[p].y, a.y);
        }
        g_Fy[(size_t)s * NZ + t] = a;
        __syncthreads();
    }
}

// =============================== so3_mm ====================================
// Computes only tiles with canonical rows (m0+7 >= l); expand mirrors the
// single non-canonical row it needs.

__global__ void __launch_bounds__(256) k_mm_all() {
    int l = blockIdx.z;
    int L = 2 * l + 1;
    int n0 = 4 * blockIdx.x;
    int m0 = 8 * blockIdx.y;
    if (m0 >= L || n0 >= L) return;
    if (m0 + 7 < l) return;           // never read -> skip
    size_t base = (size_t)base_l(l);
    __shared__ float2 Xs[8][256], Ys[4][256];
    int t = threadIdx.x;
    int b = t >> 4, g = t & 15;
    float2 c[8][4];
#pragma unroll
    for (int a = 0; a < 8; a++)
#pragma unroll
        for (int bb = 0; bb < 4; bb++) c[a][bb] = make_float2(0.f, 0.f);
    const float2 z2 = make_float2(0.f, 0.f);
    for (int k = 0; k < L; k++) {
#pragma unroll
        for (int a = 0; a < 8; a++)
            Xs[a][t] = (m0 + a < L) ? g_Fx[(base + (size_t)(m0 + a) * L + k) * NZ + t] : z2;
#pragma unroll
        for (int a = 0; a < 4; a++)
            Ys[a][t] = (n0 + a < L) ? g_Fy[(base + (size_t)k * L + (n0 + a)) * NZ + t] : z2;
        __syncthreads();
#pragma unroll
        for (int f = 0; f < 16; f++) {
            float2 xr[8], yr[4];
#pragma unroll
            for (int a = 0; a < 4; a++) yr[a] = Ys[a][f * 16 + g];
#pragma unroll
            for (int a = 0; a < 8; a++) xr[a] = Xs[a][b * 16 + f];
#pragma unroll
            for (int a = 0; a < 8; a++)
#pragma unroll
                for (int bb = 0; bb < 4; bb++) cmac(c[a][bb], xr[a], yr[bb]);
        }
        __syncthreads();
    }
#pragma unroll
    for (int a = 0; a < 8; a++) {
        if (m0 + a >= L) continue;
#pragma unroll
        for (int bb = 0; bb < 4; bb++) {
            if (n0 + bb >= L) continue;
            g_Fz[(base + (size_t)(m0 + a) * L + (n0 + bb)) * NZ + t] = c[a][bb];
        }
    }
}

// =============================== expand ====================================
// Only S rows u in [0,24] are needed by the Hermitian inverse DFT.
// su >= 0 always; the one non-canonical Fz access (su==0, sv<0) is mirrored:
// Fz[l, l+sv] = (-1)^{sv} conj Fz[l, l-sv].

__global__ void __launch_bounds__(256) k_expand() {
    int u  = blockIdx.x;              // 0..24
    int v0 = 2 * blockIdx.y;
    int su = (u < 24) ? u : u - 48;
    bool uok = (su != -24);
    int t = threadIdx.x;
    int lmin[2];
#pragma unroll
    for (int vv = 0; vv < 2; vv++) {
        int v = v0 + vv;
        int sv = (v < 24) ? v : v - 48;
        lmin[vv] = (uok && sv != -24) ? max(abs(su), abs(sv)) : 24;
    }
    __shared__ __align__(16) float ws[48][48];   // [j][2*l+vv]
    for (int i = t; i < 48 * 48; i += 256) {
        int j = i / 48, r = i - 48 * j;
        int l = r >> 1, vv = r & 1;
        float w = 0.f;
        if (l >= lmin[vv]) {
            int L = 2 * l + 1;
            int v = v0 + vv;
            int sv = (v < 24) ? v : v - 48;
            w = g_tab[OFF_WU + 48ull * (size_t)base_l(l) + ((size_t)j * L + (su + l)) * L + (sv + l)];
        }
        ws[j][r] = w;
    }
    __syncthreads();
    float4 fv[24];
#pragma unroll
    for (int l = 0; l < 24; l++) {
        fv[l] = make_float4(0.f, 0.f, 0.f, 0.f);
        int L = 2 * l + 1;
        size_t bs = (size_t)base_l(l);
#pragma unroll
        for (int vv = 0; vv < 2; vv++) {
            if (l < lmin[vv]) continue;
            int v = v0 + vv;
            int sv = (v < 24) ? v : v - 48;
            float2 f2;
            if (su == 0 && sv < 0) {
                f2 = g_Fz[(bs + (size_t)l * L + (l - sv)) * NZ + t];
                float sgn = (sv & 1) ? -1.f : 1.f;
                f2 = make_float2(sgn * f2.x, -sgn * f2.y);
            } else {
                f2 = g_Fz[(bs + (size_t)(su + l) * L + (sv + l)) * NZ + t];
            }
            if (vv) { fv[l].z = f2.x; fv[l].w = f2.y; }
            else    { fv[l].x = f2.x; fv[l].y = f2.y; }
        }
    }
    float4* Sp = g_X4 + ((size_t)t * 48 * NUV + (size_t)u * 48 + v0) / 2;
#pragma unroll 4
    for (int j = 0; j < 48; j++) {
        const float2* wj = (const float2*)ws[j];
        float4 a = make_float4(0.f, 0.f, 0.f, 0.f);
#pragma unroll
        for (int l = 0; l < 24; l++) {
            float2 w = wj[l];
            a.x = fmaf(w.x, fv[l].x, a.x);
            a.y = fmaf(w.x, fv[l].y, a.y);
            a.z = fmaf(w.y, fv[l].z, a.z);
            a.w = fmaf(w.y, fv[l].w, a.w);
        }
        Sp[(size_t)j * (NUV / 2)] = a;
    }
}

// ========================== inverse 2-D DFT ================================
// Two slices per block. Stage A: fold v with 48-v. Stage B: fold p with 48-p:
// out[p] = P + Q, out[48-p] = P - Q.  (Exact R14 tiling.)

__global__ void __launch_bounds__(256) k_fft_inv(float* __restrict__ out) {
    __shared__ __align__(16) float2 sS[2][26 * 48];
    __shared__ __align__(16) float2 sW[NUV];
    int t = threadIdx.x;
    size_t slice0 = (size_t)blockIdx.x * 2;
    const float2* Wf = (const float2*)(g_tab + OFF_WF);
    const float2* S0 = (const float2*)g_X4 + slice0 * NUV;
    const float2 z2 = make_float2(0.f, 0.f);
    for (int i = t; i < 26 * 48; i += 256) {
        bool valid = i < 25 * 48;
        sS[0][i] = valid ? S0[i] : z2;
        sS[1][i] = valid ? S0[NUV + i] : z2;
    }
    for (int i = t; i < NUV; i += 256) sW[i] = Wf[i];
    __syncthreads();
    // stage A: T[u,q] = sum_v S[u,v] conj(W[v,q]); fold v & 48-v.
    int tu = t >> 4;
    int q0 = 3 * (t & 15);
    int u0 = 2 * tu;
    float2 c[2][2][3];
    if (tu < 13) {
#pragma unroll
        for (int s = 0; s < 2; s++)
#pragma unroll
            for (int a = 0; a < 2; a++) {
                float2 S0v  = sS[s][(u0 + a) * 48];
                float2 S24v = sS[s][(u0 + a) * 48 + 24];
#pragma unroll
                for (int b = 0; b < 3; b++) {
                    float sq = ((q0 + b) & 1) ? -1.f : 1.f;
                    c[s][a][b] = make_float2(S0v.x + sq * S24v.x, S0v.y + sq * S24v.y);
                }
            }
#pragma unroll 2
        for (int v = 1; v < 24; v++) {
            float2 wq[3];
#pragma unroll
            for (int b = 0; b < 3; b++) wq[b] = sW[v * 48 + q0 + b];
#pragma unroll
            for (int s = 0; s < 2; s++)
#pragma unroll
                for (int a = 0; a < 2; a++) {
                    float2 S1 = sS[s][(u0 + a) * 48 + v];
                    float2 S2 = sS[s][(u0 + a) * 48 + 48 - v];
                    float Ex = S1.x + S2.x, Ey = S1.y + S2.y;
                    float Ox = S1.x - S2.x, Oy = S1.y - S2.y;
#pragma unroll
                    for (int b = 0; b < 3; b++) {
                        c[s][a][b].x = fmaf(Ex, wq[b].x, fmaf( Oy, wq[b].y, c[s][a][b].x));
                        c[s][a][b].y = fmaf(Ey, wq[b].x, fmaf(-Ox, wq[b].y, c[s][a][b].y));
                    }
                }
        }
    }
    __syncthreads();  // all sS reads done; reuse sS for scaled T
    if (tu < 13) {
#pragma unroll
        for (int a = 0; a < 2; a++) {
            int uu = u0 + a;
            float f = (uu == 0 || uu == 24) ? 1.f : 2.f;
#pragma unroll
            for (int s = 0; s < 2; s++)
#pragma unroll
                for (int b = 0; b < 3; b++)
                    sS[s][uu * 48 + q0 + b] = make_float2(f * c[s][a][b].x, f * c[s][a][b].y);
        }
    }
    __syncthreads();
    // stage B: P = sum_u T'x w.x, Q = sum_u T'y w.y;
    //          out[p] = (P+Q)/2304, out[48-p] = (P-Q)/2304.
    for (int i = t; i < 312; i += 256) {
        int s = (i >= 156);
        int ii = i - 156 * s;
        int p0 = 2 * (ii / 12);      // 0,2,...,24
        int qq0 = 4 * (ii % 12);
        float P[2][4], Q[2][4];
#pragma unroll
        for (int a = 0; a < 2; a++)
#pragma unroll
            for (int b = 0; b < 4; b++) { P[a][b] = 0.f; Q[a][b] = 0.f; }
#pragma unroll 5
        for (int u = 0; u < 25; u++) {
            float2 wv[2];
#pragma unroll
            for (int a = 0; a < 2; a++) wv[a] = sW[u * 48 + p0 + a];
#pragma unroll
            for (int b = 0; b < 4; b++) {
                float2 tw = sS[s][u * 48 + qq0 + b];
#pragma unroll
                for (int a = 0; a < 2; a++) {
                    P[a][b] = fmaf(tw.x, wv[a].x, P[a][b]);
                    Q[a][b] = fmaf(tw.y, wv[a].y, Q[a][b]);
                }
            }
        }
        const float scale = 1.f / 2304.f;
        float* op = out + (slice0 + s) * NUV;
#pragma unroll
        for (int a = 0; a < 2; a++) {
            int p = p0 + a;
            if (p > 24) continue;
#pragma unroll
            for (int b = 0; b < 4; b++) {
                op[p * 48 + qq0 + b] = (P[a][b] + Q[a][b]) * scale;
                if (p >= 1 && p <= 23)
                    op[(48 - p) * 48 + qq0 + b] = (P[a][b] - Q[a][b]) * scale;
            }
        }
    }
}

// ============================== launch ======================================

extern "C" void kernel_launch(void* const* d_in, const int* in_sizes, int n_in,
                              void* d_out, int out_size) {
    const float* x    = (const float*)d_in[0];
    const float* kern = (const float*)d_in[1];
    if (n_in >= 2 && in_sizes[0] == 16 * 16 * 12) {
        x = (const float*)d_in[1];
        kern = (const float*)d_in[0];
    }
    float* out = (float*)d_out;

    k_init_wf  <<<9, 256>>>();
    k_init_coef<<<24, 256>>>();
    k_init_wig <<<dim3(50, 24), 256>>>();

    k_fft_fwd  <<<NSLICE / 2, 256>>>(x);
    k_contract <<<dim3(2, 24, 24), 256>>>();
    k_fy       <<<512, 256>>>(kern);
    k_mm_all   <<<dim3(12, 6, 24), 256>>>();
    k_expand   <<<dim3(25, 24), 256>>>();
    k_fft_inv  <<<NSLICE / 2, 256>>>(out);
}

// round 17
// speedup vs baseline: 1.0682x; 1.0017x over previous
#include <cuda_runtime.h>
#include <math.h>

#define PI_D 3.14159265358979323846

// ---------------------------------------------------------------------------
// SO(3) convolution, B=24 (grid 48), F_IN=F_OUT=16, BATCH=16, P=12 rotations.
// NSPEC = sum_{l<24} (2l+1)^2 = 18424, Z = 256.
// Hermitian + conjugate-pair folding exploited in every DFT stage.
// Fz computed only for rows m in [l, 2l] (tiles anchored at the diagonal);
// expand mirrors the one non-canonical access it needs.
// ---------------------------------------------------------------------------

namespace so3 {
constexpr int    NB     = 48;
constexpr int    NSPEC  = 18424;
constexpr int    NZ     = 256;
constexpr int    NUV    = NB * NB;          // 2304
constexpr int    NSLICE = NZ * NB;          // 12288
constexpr size_t SZW    = 48ull * NSPEC;    // floats per wigner stack
constexpr size_t OFF_WW = 0;                // weighted wigner (forward)
constexpr size_t OFF_WU = SZW;              // (2l+1)-scaled wigner (inverse)
constexpr size_t OFF_RFT = 2 * SZW;         // rft matrix, float2 [12][NSPEC]
constexpr size_t OFF_WF  = OFF_RFT + 2ull * 12 * NSPEC;  // DFT twiddles float2[48*48]
constexpr size_t TABSZ   = OFF_WF + 2ull * NUV;
constexpr float  SCALING = 0.07216878364870323f;  // 1/sqrt(12*16)
}
using namespace so3;

__device__ __forceinline__ int    base_l(int l) { return (4 * l * l * l - l) / 3; }
__device__ __forceinline__ size_t base3(int l)  { return (size_t)l * l * (2 * l * l - 1); }

__device__ __forceinline__ void cmac(float2& c, const float2 a, const float2 b) {
    c.x = fmaf(a.x, b.x, fmaf(-a.y, b.y, c.x));
    c.y = fmaf(a.x, b.y, fmaf( a.y, b.x, c.y));
}

// ------------------------- static device scratch ---------------------------
__device__ float  g_tab[TABSZ];                          // ~8.9 MB
__device__ double g_coef[662976];                        // wigner coefs, fp64
__device__ float4 g_X4[(size_t)NZ * 48 * NUV / 2];       // 226 MB (X, then S)
__device__ float2 g_Fx[(size_t)NSPEC * NZ];
__device__ float2 g_Fy[(size_t)NSPEC * NZ];
__device__ float2 g_Fz[(size_t)NSPEC * NZ];

// =============================== init ======================================

__global__ void k_init_wf() {
    int t = blockIdx.x * 256 + threadIdx.x;
    if (t < NUV) {
        int a = t / 48, b = t - 48 * a;
        double ang = -2.0 * PI_D * (double)(a * b) / 48.0;
        g_tab[OFF_WF + 2 * t]     = (float)cos(ang);
        g_tab[OFF_WF + 2 * t + 1] = (float)sin(ang);
    }
}

// Only canonical quadrant (i <= jj, i + jj <= L-1) is ever read by k_init_wig.
__global__ void k_init_coef() {
    int l = blockIdx.x;
    int L = 2 * l + 1;
    __shared__ double LNF[101];
    int t = threadIdx.x;
    for (int i = t; i < 101; i += 256) LNF[i] = lgamma((double)i + 1.0);
    __syncthreads();
    double* coef = g_coef + base3(l);
    for (int e = t; e < L * L; e += 256) {
        int i = e / L, jj = e - i * L;
        if (i > jj || i + jj > L - 1) continue;   // canonical only
        int mp = i - l, mm = jj - l;
        int kmin = max(0, mm - mp), kmax = min(l + mm, l - mp);
        for (int k = kmin; k <= kmax; k++) {
            double ln = 0.5 * (LNF[l + mp] + LNF[l - mp] + LNF[l + mm] + LNF[l - mm])
                      - LNF[l + mm - k] - LNF[k] - LNF[mp - mm + k] - LNF[l - mp - k];
            double v = exp(ln);
            if ((mp - mm + k) & 1) v = -v;
            coef[(size_t)e * L + k] = v;
        }
    }
}

// jb < 48: SOFT beta grid (weighted + (2l+1)-scaled tables)
// jb = 48, 49: the two grid betas -> RFT matrix (with exact pi/3 alpha phases)
__global__ void k_init_wig() {
    int l  = blockIdx.y;
    int L  = 2 * l + 1;
    int jb = blockIdx.x;
    __shared__ double cp[47], sp[47];
    __shared__ double sw;
    int t = threadIdx.x;
    if (t == 0) {
        double beta = (jb < 48) ? ((double)jb + 0.5) * PI_D / 48.0
                                : ((jb == 48) ? PI_D / 16.0 : PI_D / 8.0);
        double c = cos(beta * 0.5), s = sin(beta * 0.5);
        double pc = 1.0, ps = 1.0;
        for (int e = 0; e < 47; e++) { cp[e] = pc; sp[e] = ps; pc *= c; ps *= s; }
        if (jb < 48) {
            double ssum = 0.0;
            for (int k = 0; k < 24; k++)
                ssum += sin((double)(2 * jb + 1) * (double)(2 * k + 1) * PI_D / 96.0)
                        / (double)(2 * k + 1);
            sw = (2.0 / 24.0) * sin(PI_D * (double)(2 * jb + 1) / 96.0) * ssum * 0.5;
        } else {
            sw = 0.0;
        }
    }
    __syncthreads();
    const double CT6[6] = {1.0, 0.5, -0.5, -1.0, -0.5, 0.5};
    const double ST6[6] = {0.0,  0.8660254037844386,  0.8660254037844386,
                           0.0, -0.8660254037844386, -0.8660254037844386};
    const double* coef = g_coef + base3(l);
    size_t wb = 48ull * (size_t)base_l(l);
    for (int e = t; e < L * L; e += 256) {
        int i = e / L, jj = e - i * L;
        if (i > jj || i + jj > L - 1) continue;   // canonical quadrant
        int mp = i - l, mm = jj - l;
        int kmin = max(0, mm - mp), kmax = min(l + mm, l - mp);
        double sum = 0.0;
        for (int k = kmin; k <= kmax; k++)
            sum += coef[(size_t)e * L + k] * cp[2 * l - 2 * k + mm - mp] * sp[2 * k + mp - mm];
        double sgn = ((i - jj) & 1) ? -sum : sum;
        int    rr[4]  = { i, jj, L - 1 - i, L - 1 - jj };
        int    ccn[4] = { jj, i, L - 1 - jj, L - 1 - i };
        double vl[4]  = { sum, sgn, sgn, sum };
        if (jb < 48) {
#pragma unroll
            for (int q = 0; q < 4; q++) {
                size_t idx = wb + ((size_t)jb * L + rr[q]) * L + ccn[q];
                g_tab[OFF_WW + idx] = (float)(vl[q] * sw);
                g_tab[OFF_WU + idx] = (float)(vl[q] * (double)L);
            }
        } else {
            int ib = jb - 48;
#pragma unroll
            for (int q = 0; q < 4; q++) {
                size_t s = (size_t)base_l(l) + (size_t)rr[q] * L + ccn[q];
                int mpr = rr[q] - l;
                for (int ia = 0; ia < 6; ia++) {
                    int n = ((mpr * ia) % 6 + 6) % 6;
                    int p = ia * 2 + ib;
                    g_tab[OFF_RFT + 2 * ((size_t)p * NSPEC + s)]     = (float)(CT6[n] * vl[q]);
                    g_tab[OFF_RFT + 2 * ((size_t)p * NSPEC + s) + 1] = (float)(ST6[n] * vl[q]);
                }
            }
        }
    }
}

// ========================== forward 2-D DFT ================================
// Two slices per block. Stage A: real even/odd fold over q, T cols v in [0,25].
// Stage B: conjugate-pair fold over p; only X rows u in [0,23] stored.

__global__ void __launch_bounds__(256) k_fft_fwd(const float* __restrict__ x) {
    __shared__ __align__(16) float  sx[2][NUV];
    __shared__ __align__(16) float2 sW[NUV];
    __shared__ __align__(16) float2 sT[2][48 * 26];
    int t = threadIdx.x;
    size_t slice0 = (size_t)blockIdx.x * 2;
    const float2* Wf = (const float2*)(g_tab + OFF_WF);
    const float* x0 = x + slice0 * NUV;
    for (int i = t; i < NUV; i += 256) {
        sx[0][i] = x0[i];
        sx[1][i] = x0[NUV + i];
        sW[i] = Wf[i];
    }
    __syncthreads();
    // stage A: T[p,v] = x0 + (-1)^v x24 + sum_{q=1..23} (e_q c, o_q (-s))
    for (int i = t; i < 312; i += 256) {
        int s = (i >= 156);
        int ii = i - 156 * s;
        int p0 = 4 * (ii / 13), v0 = 2 * (ii % 13);   // v0 even, cols v0, v0+1
        const float* xs = sx[s];
        float2 acc[4][2];
#pragma unroll
        for (int a = 0; a < 4; a++) {
            float xa0  = xs[(p0 + a) * 48];
            float xa24 = xs[(p0 + a) * 48 + 24];
            acc[a][0] = make_float2(xa0 + xa24, 0.f);   // v even
            acc[a][1] = make_float2(xa0 - xa24, 0.f);   // v odd
        }
#pragma unroll 4
        for (int q = 1; q < 24; q++) {
            float e[4], o[4];
#pragma unroll
            for (int a = 0; a < 4; a++) {
                float xa = xs[(p0 + a) * 48 + q];
                float xb = xs[(p0 + a) * 48 + 48 - q];
                e[a] = xa + xb;
                o[a] = xa - xb;
            }
            float2 w0 = sW[q * 48 + v0];
            float2 w1 = sW[q * 48 + v0 + 1];
#pragma unroll
            for (int a = 0; a < 4; a++) {
                acc[a][0].x = fmaf(e[a], w0.x, acc[a][0].x);
                acc[a][0].y = fmaf(o[a], w0.y, acc[a][0].y);
                acc[a][1].x = fmaf(e[a], w1.x, acc[a][1].x);
                acc[a][1].y = fmaf(o[a], w1.y, acc[a][1].y);
            }
        }
#pragma unroll
        for (int a = 0; a < 4; a++)
#pragma unroll
            for (int b = 0; b < 2; b++) sT[s][(p0 + a) * 26 + v0 + b] = acc[a][b];
    }
    __syncthreads();
    // stage B: X[u,v] = sum_p T[p,v] W[p,u]; fold p with 48-p. 3x3 tiles,
    // all 256 threads: s = t>>7, u0 = 3*(t128>>4) in [0,21], v0 = 3*(t128&15).
    {
        int s = t >> 7, t128 = t & 127;
        int u0 = 3 * (t128 >> 4);
        int v0 = 3 * (t128 & 15);
        int   cols[3];
        float sg[3];
#pragma unroll
        for (int b = 0; b < 3; b++) {
            int v = v0 + b;
            cols[b] = (v <= 25) ? v : 48 - v;
            sg[b]   = (v <= 25) ? 1.f : -1.f;
        }
        float2 c[3][3];
#pragma unroll
        for (int b = 0; b < 3; b++) {
            float2 t0  = sT[s][cols[b]];            // p = 0
            float2 t24 = sT[s][24 * 26 + cols[b]];  // p = 24
            t0.y *= sg[b]; t24.y *= sg[b];
#pragma unroll
            for (int a = 0; a < 3; a++) {
                float su = ((u0 + a) & 1) ? -1.f : 1.f;
                c[a][b] = make_float2(t0.x + su * t24.x, t0.y + su * t24.y);
            }
        }
#pragma unroll 2
        for (int p = 1; p < 24; p++) {
            float Ex[3], Ey[3], Ox[3], Oy[3];
#pragma unroll
            for (int b = 0; b < 3; b++) {
                float2 t1 = sT[s][p * 26 + cols[b]];
                float2 t2 = sT[s][(48 - p) * 26 + cols[b]];
                t1.y *= sg[b]; t2.y *= sg[b];
                Ex[b] = t1.x + t2.x; Ey[b] = t1.y + t2.y;
                Ox[b] = t1.x - t2.x; Oy[b] = t1.y - t2.y;
            }
#pragma unroll
            for (int a = 0; a < 3; a++) {
                float2 w = sW[p * 48 + u0 + a];
#pragma unroll
                for (int b = 0; b < 3; b++) {
                    c[a][b].x = fmaf(Ex[b], w.x, fmaf(-Oy[b], w.y, c[a][b].x));
                    c[a][b].y = fmaf(Ey[b], w.x, fmaf( Ox[b], w.y, c[a][b].y));
                }
            }
        }
        float2* Xo = (float2*)g_X4 + (slice0 + s) * NUV;
#pragma unroll
        for (int a = 0; a < 3; a++)
#pragma unroll
            for (int b = 0; b < 3; b++)
                Xo[(size_t)(u0 + a) * 48 + v0 + b] = c[a][b];
    }
}

// ========================== beta contraction ===============================
// Canonical u = su in [0,23]; mirror writes Fx[l,-su,-sv] = (-1)^{su-sv} conj.

__global__ void __launch_bounds__(256) k_contract() {
    int half = blockIdx.x;            // l in [12*half, 12*half+12)
    int u  = blockIdx.y;              // = su in 0..23
    int v0 = 2 * blockIdx.z;
    int su = u;
    int l0 = 12 * half;
    int svs[2], lmin[2];
#pragma unroll
    for (int vv = 0; vv < 2; vv++) {
        int v = v0 + vv;
        svs[vv] = (v < 24) ? v : v - 48;
        lmin[vv] = (svs[vv] == -24) ? 24 : max(su, abs(svs[vv]));
    }
    __shared__ __align__(16) float ws[48][24];   // [j][2*(l-l0)+vv]
    int t = threadIdx.x;
    for (int i = t; i < 48 * 24; i += 256) {
        int j = i / 24, r = i - 24 * j;
        int dl = r >> 1, vv = r & 1;
        int l = l0 + dl;
        float w = 0.f;
        if (l >= lmin[vv]) {
            int L = 2 * l + 1;
            w = g_tab[OFF_WW + 48ull * (size_t)base_l(l) + ((size_t)j * L + (su + l)) * L + (svs[vv] + l)];
        }
        ws[j][r] = w;
    }
    __syncthreads();
    float4 acc[12];
#pragma unroll
    for (int d = 0; d < 12; d++) acc[d] = make_float4(0.f, 0.f, 0.f, 0.f);
    const float4* Xp = g_X4 + ((size_t)t * 48 * NUV + (size_t)u * 48 + v0) / 2;
#pragma unroll 8
    for (int j = 0; j < 48; j++) {
        float4 xv = Xp[(size_t)j * (NUV / 2)];
        const float2* wj = (const float2*)ws[j];
#pragma unroll
        for (int d = 0; d < 12; d++) {
            float2 w = wj[d];
            acc[d].x = fmaf(w.x, xv.x, acc[d].x);
            acc[d].y = fmaf(w.x, xv.y, acc[d].y);
            acc[d].z = fmaf(w.y, xv.z, acc[d].z);
            acc[d].w = fmaf(w.y, xv.w, acc[d].w);
        }
    }
#pragma unroll
    for (int d = 0; d < 12; d++) {
        int l = l0 + d;
        int L = 2 * l + 1;
        size_t bs = (size_t)base_l(l);
#pragma unroll
        for (int vv = 0; vv < 2; vv++) {
            if (l < lmin[vv]) continue;
            float2 a = vv ? make_float2(acc[d].z, acc[d].w)
                          : make_float2(acc[d].x, acc[d].y);
            g_Fx[(bs + (size_t)(su + l) * L + (svs[vv] + l)) * NZ + t] = a;
            if (su > 0) {
                float sgn = ((su - svs[vv]) & 1) ? -1.f : 1.f;
                g_Fx[(bs + (size_t)(l - su) * L + (l - svs[vv])) * NZ + t] =
                    make_float2(sgn * a.x, -sgn * a.y);
            }
        }
    }
}

// ================================ Fy ========================================
// 4 spectral indices per sync iteration.

__global__ void __launch_bounds__(256) k_fy(const float* __restrict__ kern) {
    __shared__ float2 srft[4][12];
    int t = threadIdx.x;
    int f = t >> 4, g = t & 15;
    float kv[12];
#pragma unroll
    for (int p = 0; p < 12; p++) kv[p] = kern[(f * 16 + g) * 12 + p] * SCALING;
    const float2* rft = (const float2*)(g_tab + OFF_RFT);
    for (int s0 = blockIdx.x * 4; s0 < NSPEC; s0 += gridDim.x * 4) {
        if (t < 48) {
            int ss = t / 12, p = t - 12 * (t / 12);
            if (s0 + ss < NSPEC)
                srft[ss][p] = rft[(size_t)p * NSPEC + (s0 + ss)];
        }
        __syncthreads();
#pragma unroll
        for (int ss = 0; ss < 4; ss++) {
            if (s0 + ss >= NSPEC) break;
            float2 a = make_float2(0.f, 0.f);
#pragma unroll
            for (int p = 0; p < 12; p++) {
                a.x = fmaf(kv[p], srft[ss][p].x, a.x);
                a.y = fmaf(kv[p], srft[ss][p].y, a.y);
            }
            g_Fy[(size_t)(s0 + ss) * NZ + t] = a;
        }
        __syncthreads();
    }
}

// =============================== so3_mm ====================================
// Tiles anchored at the diagonal: m0 = l + 8*by covers exactly the rows
// m in [l, 2l] that expand reads. 2-k smem batching halves syncs.

__global__ void __launch_bounds__(256) k_mm_all() {
    int l = blockIdx.z;
    int L = 2 * l + 1;
    int n0 = 4 * blockIdx.x;
    int m0 = l + 8 * blockIdx.y;
    if (m0 >= L || n0 >= L) return;
    size_t base = (size_t)base_l(l);
    __shared__ float2 Xs[2][8][256], Ys[2][4][256];
    int t = threadIdx.x;
    int b = t >> 4, g = t & 15;
    float2 c[8][4];
#pragma unroll
    for (int a = 0; a < 8; a++)
#pragma unroll
        for (int bb = 0; bb < 4; bb++) c[a][bb] = make_float2(0.f, 0.f);
    const float2 z2 = make_float2(0.f, 0.f);
    for (int k0 = 0; k0 < L; k0 += 2) {
#pragma unroll
        for (int kk = 0; kk < 2; kk++) {
            int k = k0 + kk;
            if (k < L) {
#pragma unroll
                for (int a = 0; a < 8; a++)
                    Xs[kk][a][t] = (m0 + a < L) ? g_Fx[(base + (size_t)(m0 + a) * L + k) * NZ + t] : z2;
#pragma unroll
                for (int a = 0; a < 4; a++)
                    Ys[kk][a][t] = (n0 + a < L) ? g_Fy[(base + (size_t)k * L + (n0 + a)) * NZ + t] : z2;
            }
        }
        __syncthreads();
#pragma unroll
        for (int kk = 0; kk < 2; kk++) {
            if (k0 + kk < L) {
#pragma unroll
                for (int f = 0; f < 16; f++) {
                    float2 xr[8], yr[4];
#pragma unroll
                    for (int a = 0; a < 4; a++) yr[a] = Ys[kk][a][f * 16 + g];
#pragma unroll
                    for (int a = 0; a < 8; a++) xr[a] = Xs[kk][a][b * 16 + f];
#pragma unroll
                    for (int a = 0; a < 8; a++)
#pragma unroll
                        for (int bb = 0; bb < 4; bb++) cmac(c[a][bb], xr[a], yr[bb]);
                }
            }
        }
        __syncthreads();
    }
#pragma unroll
    for (int a = 0; a < 8; a++) {
        if (m0 + a >= L) continue;
#pragma unroll
        for (int bb = 0; bb < 4; bb++) {
            if (n0 + bb >= L) continue;
            g_Fz[(base + (size_t)(m0 + a) * L + (n0 + bb)) * NZ + t] = c[a][bb];
        }
    }
}

// =============================== expand ====================================
// Only S rows u in [0,24] are needed by the Hermitian inverse DFT.
// su >= 0 always; the one non-canonical Fz access (su==0, sv<0) is mirrored:
// Fz[l, l+sv] = (-1)^{sv} conj Fz[l, l-sv].

__global__ void __launch_bounds__(256) k_expand() {
    int u  = blockIdx.x;              // 0..24
    int v0 = 2 * blockIdx.y;
    int su = (u < 24) ? u : u - 48;
    bool uok = (su != -24);
    int t = threadIdx.x;
    int lmin[2];
#pragma unroll
    for (int vv = 0; vv < 2; vv++) {
        int v = v0 + vv;
        int sv = (v < 24) ? v : v - 48;
        lmin[vv] = (uok && sv != -24) ? max(abs(su), abs(sv)) : 24;
    }
    __shared__ __align__(16) float ws[48][48];   // [j][2*l+vv]
    for (int i = t; i < 48 * 48; i += 256) {
        int j = i / 48, r = i - 48 * j;
        int l = r >> 1, vv = r & 1;
        float w = 0.f;
        if (l >= lmin[vv]) {
            int L = 2 * l + 1;
            int v = v0 + vv;
            int sv = (v < 24) ? v : v - 48;
            w = g_tab[OFF_WU + 48ull * (size_t)base_l(l) + ((size_t)j * L + (su + l)) * L + (sv + l)];
        }
        ws[j][r] = w;
    }
    __syncthreads();
    float4 fv[24];
#pragma unroll
    for (int l = 0; l < 24; l++) {
        fv[l] = make_float4(0.f, 0.f, 0.f, 0.f);
        int L = 2 * l + 1;
        size_t bs = (size_t)base_l(l);
#pragma unroll
        for (int vv = 0; vv < 2; vv++) {
            if (l < lmin[vv]) continue;
            int v = v0 + vv;
            int sv = (v < 24) ? v : v - 48;
            float2 f2;
            if (su == 0 && sv < 0) {
                f2 = g_Fz[(bs + (size_t)l * L + (l - sv)) * NZ + t];
                float sgn = (sv & 1) ? -1.f : 1.f;
                f2 = make_float2(sgn * f2.x, -sgn * f2.y);
            } else {
                f2 = g_Fz[(bs + (size_t)(su + l) * L + (sv + l)) * NZ + t];
            }
            if (vv) { fv[l].z = f2.x; fv[l].w = f2.y; }
            else    { fv[l].x = f2.x; fv[l].y = f2.y; }
        }
    }
    float4* Sp = g_X4 + ((size_t)t * 48 * NUV + (size_t)u * 48 + v0) / 2;
#pragma unroll 4
    for (int j = 0; j < 48; j++) {
        const float2* wj = (const float2*)ws[j];
        float4 a = make_float4(0.f, 0.f, 0.f, 0.f);
#pragma unroll
        for (int l = 0; l < 24; l++) {
            float2 w = wj[l];
            a.x = fmaf(w.x, fv[l].x, a.x);
            a.y = fmaf(w.x, fv[l].y, a.y);
            a.z = fmaf(w.y, fv[l].z, a.z);
            a.w = fmaf(w.y, fv[l].w, a.w);
        }
        Sp[(size_t)j * (NUV / 2)] = a;
    }
}

// ========================== inverse 2-D DFT ================================
// Two slices per block. Stage A: fold v with 48-v. Stage B: fold p with 48-p:
// out[p] = P + Q, out[48-p] = P - Q.

__global__ void __launch_bounds__(256) k_fft_inv(float* __restrict__ out) {
    __shared__ __align__(16) float2 sS[2][26 * 48];
    __shared__ __align__(16) float2 sW[NUV];
    int t = threadIdx.x;
    size_t slice0 = (size_t)blockIdx.x * 2;
    const float2* Wf = (const float2*)(g_tab + OFF_WF);
    const float2* S0 = (const float2*)g_X4 + slice0 * NUV;
    const float2 z2 = make_float2(0.f, 0.f);
    for (int i = t; i < 26 * 48; i += 256) {
        bool valid = i < 25 * 48;
        sS[0][i] = valid ? S0[i] : z2;
        sS[1][i] = valid ? S0[NUV + i] : z2;
    }
    for (int i = t; i < NUV; i += 256) sW[i] = Wf[i];
    __syncthreads();
    // stage A: T[u,q] = sum_v S[u,v] conj(W[v,q]); fold v & 48-v.
    int tu = t >> 4;
    int q0 = 3 * (t & 15);
    int u0 = 2 * tu;
    float2 c[2][2][3];
    if (tu < 13) {
#pragma unroll
        for (int s = 0; s < 2; s++)
#pragma unroll
            for (int a = 0; a < 2; a++) {
                float2 S0v  = sS[s][(u0 + a) * 48];
                float2 S24v = sS[s][(u0 + a) * 48 + 24];
#pragma unroll
                for (int b = 0; b < 3; b++) {
                    float sq = ((q0 + b) & 1) ? -1.f : 1.f;
                    c[s][a][b] = make_float2(S0v.x + sq * S24v.x, S0v.y + sq * S24v.y);
                }
            }
#pragma unroll 2
        for (int v = 1; v < 24; v++) {
            float2 wq[3];
#pragma unroll
            for (int b = 0; b < 3; b++) wq[b] = sW[v * 48 + q0 + b];
#pragma unroll
            for (int s = 0; s < 2; s++)
#pragma unroll
                for (int a = 0; a < 2; a++) {
                    float2 S1 = sS[s][(u0 + a) * 48 + v];
                    float2 S2 = sS[s][(u0 + a) * 48 + 48 - v];
                    float Ex = S1.x + S2.x, Ey = S1.y + S2.y;
                    float Ox = S1.x - S2.x, Oy = S1.y - S2.y;
#pragma unroll
                    for (int b = 0; b < 3; b++) {
                        c[s][a][b].x = fmaf(Ex, wq[b].x, fmaf( Oy, wq[b].y, c[s][a][b].x));
                        c[s][a][b].y = fmaf(Ey, wq[b].x, fmaf(-Ox, wq[b].y, c[s][a][b].y));
                    }
                }
        }
    }
    __syncthreads();  // all sS reads done; reuse sS for scaled T
    if (tu < 13) {
#pragma unroll
        for (int a = 0; a < 2; a++) {
            int uu = u0 + a;
            float f = (uu == 0 || uu == 24) ? 1.f : 2.f;
#pragma unroll
            for (int s = 0; s < 2; s++)
#pragma unroll
                for (int b = 0; b < 3; b++)
                    sS[s][uu * 48 + q0 + b] = make_float2(f * c[s][a][b].x, f * c[s][a][b].y);
        }
    }
    __syncthreads();
    // stage B: P = sum_u T'x w.x, Q = sum_u T'y w.y;
    //          out[p] = (P+Q)/2304, out[48-p] = (P-Q)/2304.
    for (int i = t; i < 312; i += 256) {
        int s = (i >= 156);
        int ii = i - 156 * s;
        int p0 = 2 * (ii / 12);      // 0,2,...,24
        int qq0 = 4 * (ii % 12);
        float P[2][4], Q[2][4];
#pragma unroll
        for (int a = 0; a < 2; a++)
#pragma unroll
            for (int b = 0; b < 4; b++) { P[a][b] = 0.f; Q[a][b] = 0.f; }
#pragma unroll 5
        for (int u = 0; u < 25; u++) {
            float2 wv[2];
#pragma unroll
            for (int a = 0; a < 2; a++) wv[a] = sW[u * 48 + p0 + a];
#pragma unroll
            for (int b = 0; b < 4; b++) {
                float2 tw = sS[s][u * 48 + qq0 + b];
#pragma unroll
                for (int a = 0; a < 2; a++) {
                    P[a][b] = fmaf(tw.x, wv[a].x, P[a][b]);
                    Q[a][b] = fmaf(tw.y, wv[a].y, Q[a][b]);
                }
            }
        }
        const float scale = 1.f / 2304.f;
        float* op = out + (slice0 + s) * NUV;
#pragma unroll
        for (int a = 0; a < 2; a++) {
            int p = p0 + a;
            if (p > 24) continue;
#pragma unroll
            for (int b = 0; b < 4; b++) {
                op[p * 48 + qq0 + b] = (P[a][b] + Q[a][b]) * scale;
                if (p >= 1 && p <= 23)
                    op[(48 - p) * 48 + qq0 + b] = (P[a][b] - Q[a][b]) * scale;
            }
        }
    }
}

// ============================== launch ======================================

extern "C" void kernel_launch(void* const* d_in, const int* in_sizes, int n_in,
                              void* d_out, int out_size) {
    const float* x    = (const float*)d_in[0];
    const float* kern = (const float*)d_in[1];
    if (n_in >= 2 && in_sizes[0] == 16 * 16 * 12) {
        x = (const float*)d_in[1];
        kern = (const float*)d_in[0];
    }
    float* out = (float*)d_out;

    k_init_wf  <<<9, 256>>>();
    k_init_coef<<<24, 256>>>();
    k_init_wig <<<dim3(50, 24), 256>>>();

    k_fft_fwd  <<<NSLICE / 2, 256>>>(x);
    k_contract <<<dim3(2, 24, 24), 256>>>();
    k_fy       <<<512, 256>>>(kern);
    k_mm_all   <<<dim3(12, 3, 24), 256>>>();
    k_expand   <<<dim3(25, 24), 256>>>();
    k_fft_inv  <<<NSLICE / 2, 256>>>(out);
}